// round 10
// baseline (speedup 1.0000x reference)
#include <cuda_runtime.h>
#include <cuda_bf16.h>
#include <cstdint>

#define N_ENT 50000
#define DIM   128
#define BATCH 1024
#define NEDGE 800000
#define BN_EPS 1e-5f

#define N_TILES 391                 // ceil(50000/128)
#define N_PAD   (N_TILES * 128)     // 50048
#define READY_BIT 0x40000000
#define NCTA 148

// ---------------- static device scratch (no allocations allowed) ----------------
__device__ float g_bufA[N_ENT * DIM];   // layer GEMM outputs
__device__ float g_final[N_ENT * DIM];  // final_emb (f32, for vm gather)
__device__ float g_wmat[BATCH * DIM];   // R_emb[batch_rel] @ W
__device__ int   g_cnt[N_ENT];
__device__ int   g_rowptr[N_ENT + 1];
__device__ int   g_cur[N_ENT];
__device__ int   g_bsum[256];
__device__ int2  g_pedge[NEDGE];

// bf16 hi/lo splits (padded rows >= N_ENT stay zero from static init; never written)
__device__ __align__(16) __nv_bfloat16 g_h1H[N_PAD * DIM];      // relu(layer1) split
__device__ __align__(16) __nv_bfloat16 g_h1L[N_PAD * DIM];
__device__ __align__(16) __nv_bfloat16 g_finalH[N_PAD * DIM];
__device__ __align__(16) __nv_bfloat16 g_finalL[N_PAD * DIM];
__device__ __align__(16) __nv_bfloat16 g_vmH[BATCH * DIM];
__device__ __align__(16) __nv_bfloat16 g_vmL[BATCH * DIM];
// transposed+split weights: [n][k] k-major
__device__ __align__(16) __nv_bfloat16 g_WT1H[DIM * DIM];
__device__ __align__(16) __nv_bfloat16 g_WT1L[DIM * DIM];
__device__ __align__(16) __nv_bfloat16 g_WT2H[DIM * DIM];
__device__ __align__(16) __nv_bfloat16 g_WT2L[DIM * DIM];
__device__ __align__(16) __nv_bfloat16 g_WTWH[DIM * DIM];
__device__ __align__(16) __nv_bfloat16 g_WTWL[DIM * DIM];

// ---------------- helpers ----------------
__device__ __forceinline__ uint32_t smem_u32(const void* p) {
    uint32_t a;
    asm("{ .reg .u64 t; cvta.to.shared.u64 t, %1; cvt.u32.u64 %0, t; }" : "=r"(a) : "l"(p));
    return a;
}
__device__ __forceinline__ void ldsm_x4(uint32_t addr, uint32_t* r) {
    asm volatile("ldmatrix.sync.aligned.m8n8.x4.shared.b16 {%0,%1,%2,%3}, [%4];"
                 : "=r"(r[0]), "=r"(r[1]), "=r"(r[2]), "=r"(r[3]) : "r"(addr));
}
__device__ __forceinline__ void mma_bf16(float* d, const uint32_t* a, uint32_t b0, uint32_t b1) {
    asm volatile(
        "mma.sync.aligned.m16n8k16.row.col.f32.bf16.bf16.f32 "
        "{%0,%1,%2,%3}, {%4,%5,%6,%7}, {%8,%9}, {%0,%1,%2,%3};"
        : "+f"(d[0]), "+f"(d[1]), "+f"(d[2]), "+f"(d[3])
        : "r"(a[0]), "r"(a[1]), "r"(a[2]), "r"(a[3]), "r"(b0), "r"(b1));
}
__device__ __forceinline__ void cp16(uint32_t saddr, const void* g) {
    asm volatile("cp.async.cg.shared.global [%0], [%1], 16;" :: "r"(saddr), "l"(g) : "memory");
}
__device__ __forceinline__ float sigmoidf(float x) {
    return 1.0f / (1.0f + __expf(-x));
}
__device__ __forceinline__ uint32_t pack_bf2(float a, float b) {
    __nv_bfloat162 t = __floats2bfloat162_rn(a, b);
    return *(uint32_t*)&t;
}
__device__ __forceinline__ void split4(float4 v, uint2& hi, uint2& lo) {
    float hx = __bfloat162float(__float2bfloat16_rn(v.x));
    float hy = __bfloat162float(__float2bfloat16_rn(v.y));
    float hz = __bfloat162float(__float2bfloat16_rn(v.z));
    float hw = __bfloat162float(__float2bfloat16_rn(v.w));
    hi.x = pack_bf2(hx, hy);  hi.y = pack_bf2(hz, hw);
    lo.x = pack_bf2(v.x - hx, v.y - hy);
    lo.y = pack_bf2(v.z - hz, v.w - hw);
}

// 3-term emulated bf16 MMA over a 128x128x128 tile, 16-warp version.
// Warp grid 4(m) x 4(n); warp tile 32x32. acc[2][4][4].
__device__ __forceinline__ void mma_tile_3term16(
        uint32_t aHb, uint32_t aLb, uint32_t bHb, uint32_t bLb,
        int wm, int wn, int lrow, int lkh, float acc[2][4][4]) {
    #pragma unroll
    for (int ks = 0; ks < 8; ks++) {
        int kchunk = ks * 2 + lkh;
        uint32_t aH[2][4], aL[2][4], bH[2][4], bL[2][4];
        #pragma unroll
        for (int i = 0; i < 2; i++) {
            int row = wm * 32 + i * 16 + lrow;
            uint32_t o = row * 256 + ((kchunk ^ (row & 7)) << 4);
            ldsm_x4(aHb + o, aH[i]);
            ldsm_x4(aLb + o, aL[i]);
        }
        #pragma unroll
        for (int j2 = 0; j2 < 2; j2++) {
            int row = wn * 32 + j2 * 16 + lrow;
            uint32_t o = row * 256 + ((kchunk ^ (row & 7)) << 4);
            ldsm_x4(bHb + o, bH[j2]);
            ldsm_x4(bLb + o, bL[j2]);
        }
        #pragma unroll
        for (int i = 0; i < 2; i++)
            #pragma unroll
            for (int j = 0; j < 4; j++) {
                uint32_t h0 = bH[j >> 1][j & 1], h1 = bH[j >> 1][2 + (j & 1)];
                uint32_t l0 = bL[j >> 1][j & 1], l1 = bL[j >> 1][2 + (j & 1)];
                mma_bf16(acc[i][j], aH[i], h0, h1);
                mma_bf16(acc[i][j], aH[i], l0, l1);
                mma_bf16(acc[i][j], aL[i], h0, h1);
            }
    }
}

// ---------------- k_prep: edge histogram + weight transpose/split + g_bsum reset --------
__global__ void k_prep(const int* __restrict__ rows, int edge_blks,
                       const float* __restrict__ W1, const float* __restrict__ W2,
                       const float* __restrict__ W) {
    int tid = threadIdx.x;
    if ((int)blockIdx.x < edge_blks) {
        if (blockIdx.x == 0) g_bsum[tid] = 0;
        int gid = blockIdx.x * 256 + tid;
        if (gid < NEDGE) atomicAdd(&g_cnt[rows[gid]], 1);
    } else {
        int gid = (blockIdx.x - edge_blks) * 256 + tid;   // 0 .. 3*16384-1
        int m = gid >> 14, rem = gid & 16383, k = rem >> 7, n = rem & 127;
        const float* src = (m == 0) ? W1 : (m == 1) ? W2 : W;
        __nv_bfloat16* dh = (m == 0) ? g_WT1H : (m == 1) ? g_WT2H : g_WTWH;
        __nv_bfloat16* dl = (m == 0) ? g_WT1L : (m == 1) ? g_WT2L : g_WTWL;
        float v = src[k * DIM + n];
        __nv_bfloat16 h = __float2bfloat16_rn(v);
        dh[n * DIM + k] = h;
        dl[n * DIM + k] = __float2bfloat16_rn(v - __bfloat162float(h));
    }
}

// ---------------- single-launch scan (decoupled partials; all 196 blocks co-resident) ----
__global__ void k_scan_lb() {
    __shared__ int sh[256];
    __shared__ int red[256];
    int tid = threadIdx.x, b = blockIdx.x;
    int gid = b * 256 + tid;
    int v = (gid < N_ENT) ? g_cnt[gid] : 0;
    if (gid < N_ENT) g_cnt[gid] = 0;              // leave zeroed for next launch
    sh[tid] = v;
    __syncthreads();
    #pragma unroll
    for (int off = 1; off < 256; off <<= 1) {
        int t = 0;
        if (tid >= off) t = sh[tid - off];
        __syncthreads();
        sh[tid] += t;
        __syncthreads();
    }
    if (tid == 0) atomicExch(&g_bsum[b], sh[255] | READY_BIT);
    int myp = 0;
    if (tid < b) {
        int p;
        do { p = *(volatile int*)&g_bsum[tid]; } while (!(p & READY_BIT));
        myp = p & ~READY_BIT;
    }
    red[tid] = myp;
    __syncthreads();
    #pragma unroll
    for (int off = 128; off > 0; off >>= 1) {
        if (tid < off) red[tid] += red[tid + off];
        __syncthreads();
    }
    int prefix = red[0];
    if (gid < N_ENT) {
        int val = prefix + sh[tid] - v;
        g_rowptr[gid] = val;
        g_cur[gid] = val;
    }
    if (b == 0 && tid == 0) g_rowptr[N_ENT] = NEDGE;
}

__global__ void k_scatter(const int* __restrict__ rows, const int* __restrict__ cols,
                          const float* __restrict__ vals) {
    int gid = blockIdx.x * blockDim.x + threadIdx.x;
    if (gid < NEDGE) {
        int r = rows[gid];
        int pos = atomicAdd(&g_cur[r], 1);
        g_pedge[pos] = make_int2(cols[gid], __float_as_int(vals[gid]));
    }
}

// ---------------- persistent HMMA layer GEMM 1 (+ wmat), reg-prefetched f32 input --------
// SMEM: WH 32K | WL 32K | X buf0 H/L 64K | X buf1 H/L 64K = 192 KB.
#define P1_WH  0
#define P1_WL  32768
#define P1_X0H 65536
#define P1_X0L 98304
#define P1_X1H 131072
#define P1_X1L 163840
#define P1_SMEM 196608
#define TOT1 (N_TILES + BATCH / 128)    // 399

__global__ void __launch_bounds__(512, 1) k_hgemm1p(
        const float* __restrict__ E, const float* __restrict__ R,
        const int* __restrict__ init_ind, const int* __restrict__ batch_rel,
        float* __restrict__ outA, float* __restrict__ outW) {
    extern __shared__ char sm[];
    uint32_t smb = smem_u32(sm);
    int tid = threadIdx.x;
    int cta = blockIdx.x;

    // 399 = 103*3 + 45*2
    int start, cnt;
    if (cta < 103) { start = cta * 3; cnt = 3; }
    else           { start = 309 + (cta - 103) * 2; cnt = 2; }
    int end = start + cnt;

    int wid = tid >> 5, lane = tid & 31;
    int wm = wid >> 2, wn = wid & 3;
    int lrow = lane & 15, lkh = lane >> 4;
    int q = lane >> 2, p4 = lane & 3;

    // load W for a job into smem (sync)
    auto load_w = [&](int job) {
        const uint4* wh = (const uint4*)(job == 0 ? g_WT1H : g_WTWH);
        const uint4* wl = (const uint4*)(job == 0 ? g_WT1L : g_WTWL);
        #pragma unroll
        for (int l = tid; l < 2048; l += 512) {
            int r = l >> 4, c = l & 15;
            uint32_t off = r * 256 + ((c ^ (r & 7)) << 4);
            *(uint4*)(sm + P1_WH + off) = wh[l];
            *(uint4*)(sm + P1_WL + off) = wl[l];
        }
    };
    // load tile t's X rows into registers (8 float4 per thread)
    float4 rx[8];
    auto load_x = [&](int t) {
        int job = (t < N_TILES) ? 0 : 1;
        const float* X = job == 0 ? E : R;
        const int* idx = job == 0 ? init_ind : batch_rel;
        int nrows = job == 0 ? N_ENT : BATCH;
        int rbase = job == 0 ? t * 128 : (t - N_TILES) * 128;
        #pragma unroll
        for (int k = 0; k < 4; k++) {
            int l = tid + k * 512;
            int r = l >> 4, c = l & 15;
            int gr = rbase + r;
            float4 v0 = make_float4(0.f, 0.f, 0.f, 0.f), v1 = v0;
            if (gr < nrows) {
                const float4* xp = (const float4*)X + (size_t)idx[gr] * 32 + c * 2;
                v0 = xp[0]; v1 = xp[1];
            }
            rx[k * 2] = v0; rx[k * 2 + 1] = v1;
        }
    };

    int cur_job = (start < N_TILES) ? 0 : 1;
    load_w(cur_job);
    load_x(start);
    int p = 0;

    for (int t = start; t < end; t++) {
        int job = (t < N_TILES) ? 0 : 1;
        if (job != cur_job) {
            __syncthreads();
            load_w(job);
            cur_job = job;
        }
        // split registers into X smem buffer p
        uint32_t xh = smb + (p ? P1_X1H : P1_X0H);
        uint32_t xl = smb + (p ? P1_X1L : P1_X0L);
        #pragma unroll
        for (int k = 0; k < 4; k++) {
            int l = tid + k * 512;
            int r = l >> 4, c = l & 15;
            uint32_t off = r * 256 + ((c ^ (r & 7)) << 4);
            uint2 h0, l0, h1, l1;
            split4(rx[k * 2], h0, l0); split4(rx[k * 2 + 1], h1, l1);
            *(uint4*)((char*)sm + (xh - smb) + off) = make_uint4(h0.x, h0.y, h1.x, h1.y);
            *(uint4*)((char*)sm + (xl - smb) + off) = make_uint4(l0.x, l0.y, l1.x, l1.y);
        }
        __syncthreads();

        // issue next tile's global loads (overlaps MMA below)
        if (t + 1 < end) load_x(t + 1);

        float acc[2][4][4];
        #pragma unroll
        for (int i = 0; i < 2; i++)
            #pragma unroll
            for (int j = 0; j < 4; j++)
                #pragma unroll
                for (int f = 0; f < 4; f++) acc[i][j][f] = 0.f;

        mma_tile_3term16(xh, xl, smb + P1_WH, smb + P1_WL, wm, wn, lrow, lkh, acc);

        // epilogue
        float* out = (job == 0) ? outA : outW;
        int nrows = (job == 0) ? N_ENT : BATCH;
        int rbase = (job == 0) ? t * 128 : (t - N_TILES) * 128;
        #pragma unroll
        for (int i = 0; i < 2; i++) {
            int r0 = rbase + wm * 32 + i * 16 + q;
            #pragma unroll
            for (int j = 0; j < 4; j++) {
                int n = wn * 32 + j * 8 + p4 * 2;
                if (r0 < nrows)
                    *(float2*)(out + (size_t)r0 * DIM + n) = make_float2(acc[i][j][0], acc[i][j][1]);
                if (r0 + 8 < nrows)
                    *(float2*)(out + (size_t)(r0 + 8) * DIM + n) = make_float2(acc[i][j][2], acc[i][j][3]);
            }
        }
        p ^= 1;
    }
}

// ---------------- persistent HMMA layer GEMM 2, cp.async bf16 input ----------------
// SMEM: WH 32K | WL 32K | X buf0 (H+L) 64K | X buf1 (H+L) 64K = 192 KB.
#define P2_WH 0
#define P2_WL 32768
#define P2_X0 65536
#define P2_X1 131072
#define P2_SMEM 196608

__global__ void __launch_bounds__(512, 1) k_hgemm2p(float* __restrict__ out) {
    extern __shared__ char sm[];
    uint32_t smb = smem_u32(sm);
    int tid = threadIdx.x;
    int cta = blockIdx.x;

    // 391 = 95*3 + 53*2
    int start, cnt;
    if (cta < 95) { start = cta * 3; cnt = 3; }
    else          { start = 285 + (cta - 95) * 2; cnt = 2; }
    int end = start + cnt;

    int wid = tid >> 5, lane = tid & 31;
    int wm = wid >> 2, wn = wid & 3;
    int lrow = lane & 15, lkh = lane >> 4;
    int q = lane >> 2, p4 = lane & 3;

    const uint4* xh = (const uint4*)g_h1H;
    const uint4* xl = (const uint4*)g_h1L;

    auto prefetch_x = [&](int t, uint32_t dst) {
        size_t base = (size_t)t * 2048;          // 128 rows * 16 chunks
        #pragma unroll
        for (int l = tid; l < 2048; l += 512) {
            int r = l >> 4, c = l & 15;
            uint32_t off = r * 256 + ((c ^ (r & 7)) << 4);
            cp16(dst + off,         xh + base + l);
            cp16(dst + 32768 + off, xl + base + l);
        }
    };

    // prologue: W2 + first X tile
    {
        const uint4* wh = (const uint4*)g_WT2H;
        const uint4* wl = (const uint4*)g_WT2L;
        #pragma unroll
        for (int l = tid; l < 2048; l += 512) {
            int r = l >> 4, c = l & 15;
            uint32_t off = r * 256 + ((c ^ (r & 7)) << 4);
            cp16(smb + P2_WH + off, wh + l);
            cp16(smb + P2_WL + off, wl + l);
        }
        prefetch_x(start, smb + P2_X0);
        asm volatile("cp.async.commit_group;" ::: "memory");
        asm volatile("cp.async.wait_group 0;" ::: "memory");
    }
    __syncthreads();

    int p = 0;
    for (int t = start; t < end; t++) {
        if (t + 1 < end) {
            prefetch_x(t + 1, smb + (p ? P2_X0 : P2_X1));
            asm volatile("cp.async.commit_group;" ::: "memory");
        }

        uint32_t xb = smb + (p ? P2_X1 : P2_X0);
        float acc[2][4][4];
        #pragma unroll
        for (int i = 0; i < 2; i++)
            #pragma unroll
            for (int j = 0; j < 4; j++)
                #pragma unroll
                for (int f = 0; f < 4; f++) acc[i][j][f] = 0.f;

        mma_tile_3term16(xb, xb + 32768, smb + P2_WH, smb + P2_WL, wm, wn, lrow, lkh, acc);

        int rbase = t * 128;
        #pragma unroll
        for (int i = 0; i < 2; i++) {
            int r0 = rbase + wm * 32 + i * 16 + q;
            #pragma unroll
            for (int j = 0; j < 4; j++) {
                int n = wn * 32 + j * 8 + p4 * 2;
                if (r0 < N_ENT)
                    *(float2*)(out + (size_t)r0 * DIM + n) = make_float2(acc[i][j][0], acc[i][j][1]);
                if (r0 + 8 < N_ENT)
                    *(float2*)(out + (size_t)(r0 + 8) * DIM + n) = make_float2(acc[i][j][2], acc[i][j][3]);
            }
        }

        if (t + 1 < end) {
            asm volatile("cp.async.wait_group 0;" ::: "memory");
            __syncthreads();   // next data ready AND all warps done with current MMA
        }
        p ^= 1;
    }
}

// ---------------- SpMM 1: h1 = split(relu(b1 + A @ src)), 4-way unrolled ----------------
__global__ void k_spmm1(const float* __restrict__ src, const float* __restrict__ bias) {
    int w = (blockIdx.x * blockDim.x + threadIdx.x) >> 5;
    int lane = threadIdx.x & 31;
    if (w >= N_ENT) return;
    int s = g_rowptr[w], e = g_rowptr[w + 1];
    const float4* s4 = (const float4*)src;
    float4 a0 = ((const float4*)bias)[lane];
    float4 a1 = make_float4(0.f, 0.f, 0.f, 0.f), a2 = a1, a3 = a1;
    int j = s;
    for (; j + 4 <= e; j += 4) {
        int2 p0 = g_pedge[j], p1 = g_pedge[j + 1], p2 = g_pedge[j + 2], p3 = g_pedge[j + 3];
        float4 x0 = s4[(size_t)p0.x * 32 + lane];
        float4 x1 = s4[(size_t)p1.x * 32 + lane];
        float4 x2 = s4[(size_t)p2.x * 32 + lane];
        float4 x3 = s4[(size_t)p3.x * 32 + lane];
        float v0 = __int_as_float(p0.y), v1 = __int_as_float(p1.y);
        float v2 = __int_as_float(p2.y), v3 = __int_as_float(p3.y);
        a0.x += v0 * x0.x; a0.y += v0 * x0.y; a0.z += v0 * x0.z; a0.w += v0 * x0.w;
        a1.x += v1 * x1.x; a1.y += v1 * x1.y; a1.z += v1 * x1.z; a1.w += v1 * x1.w;
        a2.x += v2 * x2.x; a2.y += v2 * x2.y; a2.z += v2 * x2.z; a2.w += v2 * x2.w;
        a3.x += v3 * x3.x; a3.y += v3 * x3.y; a3.z += v3 * x3.z; a3.w += v3 * x3.w;
    }
    for (; j < e; j++) {
        int2 pe = g_pedge[j];
        float v = __int_as_float(pe.y);
        float4 x = s4[(size_t)pe.x * 32 + lane];
        a0.x += v * x.x; a0.y += v * x.y; a0.z += v * x.z; a0.w += v * x.w;
    }
    a0.x += a1.x + a2.x + a3.x; a0.y += a1.y + a2.y + a3.y;
    a0.z += a1.z + a2.z + a3.z; a0.w += a1.w + a2.w + a3.w;
    a0.x = fmaxf(a0.x, 0.f); a0.y = fmaxf(a0.y, 0.f);
    a0.z = fmaxf(a0.z, 0.f); a0.w = fmaxf(a0.w, 0.f);
    uint2 hi, lo;
    split4(a0, hi, lo);
    ((uint2*)g_h1H)[w * 32 + lane] = hi;
    ((uint2*)g_h1L)[w * 32 + lane] = lo;
}

// ---------------- SpMM 2 fused: final = E[init] + relu(b2 + A @ src); + split ----------
__global__ void k_spmm2f(const float* __restrict__ src, const float* __restrict__ bias,
                         const float* __restrict__ E, const int* __restrict__ idx) {
    int w = (blockIdx.x * blockDim.x + threadIdx.x) >> 5;
    int lane = threadIdx.x & 31;
    if (w >= N_ENT) return;
    int s = g_rowptr[w], e = g_rowptr[w + 1];
    const float4* s4 = (const float4*)src;
    float4 a0 = ((const float4*)bias)[lane];
    float4 a1 = make_float4(0.f, 0.f, 0.f, 0.f), a2 = a1, a3 = a1;
    int j = s;
    for (; j + 4 <= e; j += 4) {
        int2 p0 = g_pedge[j], p1 = g_pedge[j + 1], p2 = g_pedge[j + 2], p3 = g_pedge[j + 3];
        float4 x0 = s4[(size_t)p0.x * 32 + lane];
        float4 x1 = s4[(size_t)p1.x * 32 + lane];
        float4 x2 = s4[(size_t)p2.x * 32 + lane];
        float4 x3 = s4[(size_t)p3.x * 32 + lane];
        float v0 = __int_as_float(p0.y), v1 = __int_as_float(p1.y);
        float v2 = __int_as_float(p2.y), v3 = __int_as_float(p3.y);
        a0.x += v0 * x0.x; a0.y += v0 * x0.y; a0.z += v0 * x0.z; a0.w += v0 * x0.w;
        a1.x += v1 * x1.x; a1.y += v1 * x1.y; a1.z += v1 * x1.z; a1.w += v1 * x1.w;
        a2.x += v2 * x2.x; a2.y += v2 * x2.y; a2.z += v2 * x2.z; a2.w += v2 * x2.w;
        a3.x += v3 * x3.x; a3.y += v3 * x3.y; a3.z += v3 * x3.z; a3.w += v3 * x3.w;
    }
    for (; j < e; j++) {
        int2 pe = g_pedge[j];
        float v = __int_as_float(pe.y);
        float4 x = s4[(size_t)pe.x * 32 + lane];
        a0.x += v * x.x; a0.y += v * x.y; a0.z += v * x.z; a0.w += v * x.w;
    }
    a0.x += a1.x + a2.x + a3.x; a0.y += a1.y + a2.y + a3.y;
    a0.z += a1.z + a2.z + a3.z; a0.w += a1.w + a2.w + a3.w;
    float4 e4 = ((const float4*)E)[(size_t)idx[w] * 32 + lane];
    e4.x += fmaxf(a0.x, 0.f); e4.y += fmaxf(a0.y, 0.f);
    e4.z += fmaxf(a0.z, 0.f); e4.w += fmaxf(a0.w, 0.f);
    ((float4*)g_final)[w * 32 + lane] = e4;
    uint2 hi, lo;
    split4(e4, hi, lo);
    ((uint2*)g_finalH)[w * 32 + lane] = hi;
    ((uint2*)g_finalL)[w * 32 + lane] = lo;
}

// ---------------- vm = bn1(bn0(final[bh]) * wmat); + split ----------------
__global__ void k_vm_split(const int* __restrict__ bh,
                           const float* __restrict__ g0, const float* __restrict__ b0,
                           const float* __restrict__ g1, const float* __restrict__ b1) {
    int gid = blockIdx.x * blockDim.x + threadIdx.x;
    if (gid >= BATCH * 32) return;
    int b = gid >> 5, qq = gid & 31;
    float s = rsqrtf(1.0f + BN_EPS);
    float4 G0 = ((const float4*)g0)[qq], B0 = ((const float4*)b0)[qq];
    float4 G1 = ((const float4*)g1)[qq], B1 = ((const float4*)b1)[qq];
    float4 x = ((const float4*)g_final)[(size_t)bh[b] * 32 + qq];
    float4 wm = ((const float4*)g_wmat)[gid];
    float4 r;
    r.x = ((x.x * (G0.x * s) + B0.x) * wm.x) * (G1.x * s) + B1.x;
    r.y = ((x.y * (G0.y * s) + B0.y) * wm.y) * (G1.y * s) + B1.y;
    r.z = ((x.z * (G0.z * s) + B0.z) * wm.z) * (G1.z * s) + B1.z;
    r.w = ((x.w * (G0.w * s) + B0.w) * wm.w) * (G1.w * s) + B1.w;
    uint2 hi, lo;
    split4(r, hi, lo);
    ((uint2*)g_vmH)[gid] = hi;
    ((uint2*)g_vmL)[gid] = lo;
}

// ---------------- persistent double-buffered big GEMM, 512 thr --------------------------
#define PG_AH 0
#define PG_AL 32768
#define PG_B0 65536
#define PG_B1 131072
#define PG_SMEM 196608

__global__ void __launch_bounds__(512, 1) k_biggemm_persist(float* __restrict__ out) {
    extern __shared__ char sm[];
    uint32_t smb = smem_u32(sm);
    int tid = threadIdx.x;
    int cta = blockIdx.x;

    // balanced contiguous chunks: 3128 = 20*22 + 128*21
    int start, cnt;
    if (cta < 20) { start = cta * 22; cnt = 22; }
    else          { start = 440 + (cta - 20) * 21; cnt = 21; }
    int end = start + cnt;

    const uint4* Ah = (const uint4*)g_vmH;
    const uint4* Al = (const uint4*)g_vmL;
    const uint4* Bh = (const uint4*)g_finalH;
    const uint4* Bl = (const uint4*)g_finalL;

    int wid = tid >> 5, lane = tid & 31;
    int wm = wid >> 2, wn = wid & 3;
    int lrow = lane & 15, lkh = lane >> 4;
    int q = lane >> 2, p4 = lane & 3;

    int cur_b = -1, buf = 0, loaded = 0;

    for (int t = start; t < end; t++) {
        int b = t / N_TILES, n = t - b * N_TILES;
        __syncthreads();

        if (!loaded) {
            if (b != cur_b) {
                int bbase = b * 128;
                #pragma unroll
                for (int l = tid; l < 2048; l += 512) {
                    int r = l >> 4, c = l & 15;
                    uint32_t off = r * 256 + ((c ^ (r & 7)) << 4);
                    cp16(smb + PG_AH + off, Ah + (size_t)(bbase + r) * 16 + c);
                    cp16(smb + PG_AL + off, Al + (size_t)(bbase + r) * 16 + c);
                }
                cur_b = b;
            }
            int nbase = n * 128;
            uint32_t sb = smb + (buf ? PG_B1 : PG_B0);
            #pragma unroll
            for (int l = tid; l < 2048; l += 512) {
                int r = l >> 4, c = l & 15;
                uint32_t off = r * 256 + ((c ^ (r & 7)) << 4);
                cp16(sb + off,         Bh + (size_t)(nbase + r) * 16 + c);
                cp16(sb + 32768 + off, Bl + (size_t)(nbase + r) * 16 + c);
            }
            asm volatile("cp.async.commit_group;" ::: "memory");
        }

        int pf = 0;
        if (t + 1 < end) {
            int b2 = (t + 1) / N_TILES, n2 = (t + 1) - b2 * N_TILES;
            if (b2 == cur_b) {
                int nbase2 = n2 * 128;
                uint32_t sb2 = smb + (buf ? PG_B0 : PG_B1);
                #pragma unroll
                for (int l = tid; l < 2048; l += 512) {
                    int r = l >> 4, c = l & 15;
                    uint32_t off = r * 256 + ((c ^ (r & 7)) << 4);
                    cp16(sb2 + off,         Bh + (size_t)(nbase2 + r) * 16 + c);
                    cp16(sb2 + 32768 + off, Bl + (size_t)(nbase2 + r) * 16 + c);
                }
                asm volatile("cp.async.commit_group;" ::: "memory");
                pf = 1;
            }
        }
        if (pf) asm volatile("cp.async.wait_group 1;" ::: "memory");
        else    asm volatile("cp.async.wait_group 0;" ::: "memory");
        __syncthreads();

        uint32_t sb = smb + (buf ? PG_B1 : PG_B0);
        float acc[2][4][4];
        #pragma unroll
        for (int i = 0; i < 2; i++)
            #pragma unroll
            for (int j = 0; j < 4; j++)
                #pragma unroll
                for (int f = 0; f < 4; f++) acc[i][j][f] = 0.f;

        mma_tile_3term16(smb + PG_AH, smb + PG_AL, sb, sb + 32768,
                         wm, wn, lrow, lkh, acc);

        int bbase = b * 128, nbase = n * 128;
        #pragma unroll
        for (int i = 0; i < 2; i++) {
            int brow = bbase + wm * 32 + i * 16 + q;
            #pragma unroll
            for (int j = 0; j < 4; j++) {
                int nn = nbase + wn * 32 + j * 8 + p4 * 2;
                if (nn < N_ENT) {
                    float2 o0, o1;
                    o0.x = sigmoidf(acc[i][j][0]); o0.y = sigmoidf(acc[i][j][1]);
                    o1.x = sigmoidf(acc[i][j][2]); o1.y = sigmoidf(acc[i][j][3]);
                    *(float2*)(out + (size_t)brow * N_ENT + nn) = o0;
                    *(float2*)(out + (size_t)(brow + 8) * N_ENT + nn) = o1;
                }
            }
        }

        loaded = pf;
        buf ^= 1;
    }
}

// ---------------- orchestration ----------------
extern "C" void kernel_launch(void* const* d_in, const int* in_sizes, int n_in,
                              void* d_out, int out_size) {
    const float* E_emb     = (const float*)d_in[0];
    const float* R_emb     = (const float*)d_in[1];
    const float* W1        = (const float*)d_in[2];
    const float* b1        = (const float*)d_in[3];
    const float* W2        = (const float*)d_in[4];
    const float* b2        = (const float*)d_in[5];
    const float* W         = (const float*)d_in[6];
    const float* adj_vals  = (const float*)d_in[7];
    const float* bn0_gamma = (const float*)d_in[8];
    const float* bn0_beta  = (const float*)d_in[9];
    const float* bn1_gamma = (const float*)d_in[10];
    const float* bn1_beta  = (const float*)d_in[11];
    const int*   batch_head = (const int*)d_in[12];
    const int*   batch_rel  = (const int*)d_in[13];
    const int*   init_ind   = (const int*)d_in[14];
    const int*   adj_rows   = (const int*)d_in[15];
    const int*   adj_cols   = (const int*)d_in[16];
    float* out = (float*)d_out;

    float *pA, *pWM;
    cudaGetSymbolAddress((void**)&pA, g_bufA);
    cudaGetSymbolAddress((void**)&pWM, g_wmat);

    cudaFuncSetAttribute(k_hgemm1p, cudaFuncAttributeMaxDynamicSharedMemorySize, P1_SMEM);
    cudaFuncSetAttribute(k_hgemm2p, cudaFuncAttributeMaxDynamicSharedMemorySize, P2_SMEM);
    cudaFuncSetAttribute(k_biggemm_persist, cudaFuncAttributeMaxDynamicSharedMemorySize, PG_SMEM);

    const int EDGE_BLKS = (NEDGE + 255) / 256;          // 3125
    const int ENT_BLKS  = (N_ENT + 255) / 256;          // 196
    const int ROWW_BLKS = (N_ENT * 32 + 255) / 256;     // 6250

    // 1. histogram + weight splits (+ g_bsum reset)
    k_prep<<<EDGE_BLKS + 192, 256>>>(adj_rows, EDGE_BLKS, W1, W2, W);
    // 2. single-launch scan (also zeroes g_cnt for next launch)
    k_scan_lb<<<ENT_BLKS, 256>>>();
    // 3. CSR scatter
    k_scatter<<<EDGE_BLKS, 256>>>(adj_rows, adj_cols, adj_vals);
    // 4. persistent layer-1 GEMM + wmat GEMM
    k_hgemm1p<<<NCTA, 512, P1_SMEM>>>(E_emb, R_emb, init_ind, batch_rel, pA, pWM);
    // 5. SpMM1 (+relu+split)
    k_spmm1<<<ROWW_BLKS, 256>>>(pA, b1);
    // 6. persistent layer-2 GEMM (bf16 in, f32 out)
    k_hgemm2p<<<NCTA, 512, P2_SMEM>>>(pA);
    // 7. SpMM2 (+residual+relu+split)
    k_spmm2f<<<ROWW_BLKS, 256>>>(pA, b2, E_emb, init_ind);
    // 8. vm (+split)
    k_vm_split<<<(BATCH * 32 + 255) / 256, 256>>>(batch_head, bn0_gamma, bn0_beta, bn1_gamma, bn1_beta);
    // 9. persistent tensor-core scoring GEMM + sigmoid
    k_biggemm_persist<<<NCTA, 512, PG_SMEM>>>(out);
}

// round 11
// speedup vs baseline: 1.0224x; 1.0224x over previous
#include <cuda_runtime.h>
#include <cuda_bf16.h>
#include <cstdint>

#define N_ENT 50000
#define DIM   128
#define BATCH 1024
#define NEDGE 800000
#define BN_EPS 1e-5f

#define N_TILES 391                 // ceil(50000/128)
#define N_PAD   (N_TILES * 128)     // 50048
#define READY_BIT 0x40000000
#define NCTA 148
#define QS    4096.0f
#define INV_QS (1.0f / 4096.0f)

// ---------------- static device scratch (no allocations allowed) ----------------
__device__ __align__(16) short g_bufA[N_ENT * DIM];   // layer GEMM outputs, int16 x4096
__device__ float g_wmat[BATCH * DIM];   // R_emb[batch_rel] @ W
__device__ int   g_cnt[N_ENT];
__device__ int   g_rowptr[N_ENT + 1];
__device__ int   g_cur[N_ENT];
__device__ int   g_bsum[256];
__device__ int2  g_pedge[NEDGE];

// bf16 hi/lo splits (padded rows >= N_ENT stay zero from static init; never written)
__device__ __align__(16) __nv_bfloat16 g_h1H[N_PAD * DIM];      // relu(layer1) split
__device__ __align__(16) __nv_bfloat16 g_h1L[N_PAD * DIM];
__device__ __align__(16) __nv_bfloat16 g_finalH[N_PAD * DIM];
__device__ __align__(16) __nv_bfloat16 g_finalL[N_PAD * DIM];
__device__ __align__(16) __nv_bfloat16 g_vmH[BATCH * DIM];
__device__ __align__(16) __nv_bfloat16 g_vmL[BATCH * DIM];
// transposed+split weights: [n][k] k-major
__device__ __align__(16) __nv_bfloat16 g_WT1H[DIM * DIM];
__device__ __align__(16) __nv_bfloat16 g_WT1L[DIM * DIM];
__device__ __align__(16) __nv_bfloat16 g_WT2H[DIM * DIM];
__device__ __align__(16) __nv_bfloat16 g_WT2L[DIM * DIM];
__device__ __align__(16) __nv_bfloat16 g_WTWH[DIM * DIM];
__device__ __align__(16) __nv_bfloat16 g_WTWL[DIM * DIM];

// ---------------- helpers ----------------
__device__ __forceinline__ uint32_t smem_u32(const void* p) {
    uint32_t a;
    asm("{ .reg .u64 t; cvta.to.shared.u64 t, %1; cvt.u32.u64 %0, t; }" : "=r"(a) : "l"(p));
    return a;
}
__device__ __forceinline__ void ldsm_x4(uint32_t addr, uint32_t* r) {
    asm volatile("ldmatrix.sync.aligned.m8n8.x4.shared.b16 {%0,%1,%2,%3}, [%4];"
                 : "=r"(r[0]), "=r"(r[1]), "=r"(r[2]), "=r"(r[3]) : "r"(addr));
}
__device__ __forceinline__ void mma_bf16(float* d, const uint32_t* a, uint32_t b0, uint32_t b1) {
    asm volatile(
        "mma.sync.aligned.m16n8k16.row.col.f32.bf16.bf16.f32 "
        "{%0,%1,%2,%3}, {%4,%5,%6,%7}, {%8,%9}, {%0,%1,%2,%3};"
        : "+f"(d[0]), "+f"(d[1]), "+f"(d[2]), "+f"(d[3])
        : "r"(a[0]), "r"(a[1]), "r"(a[2]), "r"(a[3]), "r"(b0), "r"(b1));
}
__device__ __forceinline__ void cp16(uint32_t saddr, const void* g) {
    asm volatile("cp.async.cg.shared.global [%0], [%1], 16;" :: "r"(saddr), "l"(g) : "memory");
}
__device__ __forceinline__ float sigmoidf(float x) {
    return 1.0f / (1.0f + __expf(-x));
}
__device__ __forceinline__ uint32_t pack_bf2(float a, float b) {
    __nv_bfloat162 t = __floats2bfloat162_rn(a, b);
    return *(uint32_t*)&t;
}
__device__ __forceinline__ void split4(float4 v, uint2& hi, uint2& lo) {
    float hx = __bfloat162float(__float2bfloat16_rn(v.x));
    float hy = __bfloat162float(__float2bfloat16_rn(v.y));
    float hz = __bfloat162float(__float2bfloat16_rn(v.z));
    float hw = __bfloat162float(__float2bfloat16_rn(v.w));
    hi.x = pack_bf2(hx, hy);  hi.y = pack_bf2(hz, hw);
    lo.x = pack_bf2(v.x - hx, v.y - hy);
    lo.y = pack_bf2(v.z - hz, v.w - hw);
}
__device__ __forceinline__ float4 unsplit4(uint2 h, uint2 l) {
    __nv_bfloat162 h0 = *(__nv_bfloat162*)&h.x, h1 = *(__nv_bfloat162*)&h.y;
    __nv_bfloat162 l0 = *(__nv_bfloat162*)&l.x, l1 = *(__nv_bfloat162*)&l.y;
    float4 r;
    r.x = __bfloat162float(h0.x) + __bfloat162float(l0.x);
    r.y = __bfloat162float(h0.y) + __bfloat162float(l0.y);
    r.z = __bfloat162float(h1.x) + __bfloat162float(l1.x);
    r.w = __bfloat162float(h1.y) + __bfloat162float(l1.y);
    return r;
}
// pack two f32 into int16x2 scaled by QS (clamped to ±7.99)
__device__ __forceinline__ uint32_t q2(float a, float b) {
    int ia = __float2int_rn(fminf(fmaxf(a, -7.99f), 7.99f) * QS);
    int ib = __float2int_rn(fminf(fmaxf(b, -7.99f), 7.99f) * QS);
    return (uint32_t)(ia & 0xFFFF) | ((uint32_t)ib << 16);
}

// 3-term emulated bf16 MMA over a 128x128x128 tile, 16-warp version.
// Warp grid 4(m) x 4(n); warp tile 32x32. acc[2][4][4].
__device__ __forceinline__ void mma_tile_3term16(
        uint32_t aHb, uint32_t aLb, uint32_t bHb, uint32_t bLb,
        int wm, int wn, int lrow, int lkh, float acc[2][4][4]) {
    #pragma unroll
    for (int ks = 0; ks < 8; ks++) {
        int kchunk = ks * 2 + lkh;
        uint32_t aH[2][4], aL[2][4], bH[2][4], bL[2][4];
        #pragma unroll
        for (int i = 0; i < 2; i++) {
            int row = wm * 32 + i * 16 + lrow;
            uint32_t o = row * 256 + ((kchunk ^ (row & 7)) << 4);
            ldsm_x4(aHb + o, aH[i]);
            ldsm_x4(aLb + o, aL[i]);
        }
        #pragma unroll
        for (int j2 = 0; j2 < 2; j2++) {
            int row = wn * 32 + j2 * 16 + lrow;
            uint32_t o = row * 256 + ((kchunk ^ (row & 7)) << 4);
            ldsm_x4(bHb + o, bH[j2]);
            ldsm_x4(bLb + o, bL[j2]);
        }
        #pragma unroll
        for (int i = 0; i < 2; i++)
            #pragma unroll
            for (int j = 0; j < 4; j++) {
                uint32_t h0 = bH[j >> 1][j & 1], h1 = bH[j >> 1][2 + (j & 1)];
                uint32_t l0 = bL[j >> 1][j & 1], l1 = bL[j >> 1][2 + (j & 1)];
                mma_bf16(acc[i][j], aH[i], h0, h1);
                mma_bf16(acc[i][j], aH[i], l0, l1);
                mma_bf16(acc[i][j], aL[i], h0, h1);
            }
    }
}

// ---------------- k_prep: edge histogram + weight transpose/split + g_bsum reset --------
__global__ void k_prep(const int* __restrict__ rows, int edge_blks,
                       const float* __restrict__ W1, const float* __restrict__ W2,
                       const float* __restrict__ W) {
    int tid = threadIdx.x;
    if ((int)blockIdx.x < edge_blks) {
        if (blockIdx.x == 0) g_bsum[tid] = 0;
        int gid = blockIdx.x * 256 + tid;
        if (gid < NEDGE) atomicAdd(&g_cnt[rows[gid]], 1);
    } else {
        int gid = (blockIdx.x - edge_blks) * 256 + tid;   // 0 .. 3*16384-1
        int m = gid >> 14, rem = gid & 16383, k = rem >> 7, n = rem & 127;
        const float* src = (m == 0) ? W1 : (m == 1) ? W2 : W;
        __nv_bfloat16* dh = (m == 0) ? g_WT1H : (m == 1) ? g_WT2H : g_WTWH;
        __nv_bfloat16* dl = (m == 0) ? g_WT1L : (m == 1) ? g_WT2L : g_WTWL;
        float v = src[k * DIM + n];
        __nv_bfloat16 h = __float2bfloat16_rn(v);
        dh[n * DIM + k] = h;
        dl[n * DIM + k] = __float2bfloat16_rn(v - __bfloat162float(h));
    }
}

// ---------------- single-launch scan (decoupled partials; all 196 blocks co-resident) ----
__global__ void k_scan_lb() {
    __shared__ int sh[256];
    __shared__ int red[256];
    int tid = threadIdx.x, b = blockIdx.x;
    int gid = b * 256 + tid;
    int v = (gid < N_ENT) ? g_cnt[gid] : 0;
    if (gid < N_ENT) g_cnt[gid] = 0;              // leave zeroed for next launch
    sh[tid] = v;
    __syncthreads();
    #pragma unroll
    for (int off = 1; off < 256; off <<= 1) {
        int t = 0;
        if (tid >= off) t = sh[tid - off];
        __syncthreads();
        sh[tid] += t;
        __syncthreads();
    }
    if (tid == 0) atomicExch(&g_bsum[b], sh[255] | READY_BIT);
    int myp = 0;
    if (tid < b) {
        int p;
        do { p = *(volatile int*)&g_bsum[tid]; } while (!(p & READY_BIT));
        myp = p & ~READY_BIT;
    }
    red[tid] = myp;
    __syncthreads();
    #pragma unroll
    for (int off = 128; off > 0; off >>= 1) {
        if (tid < off) red[tid] += red[tid + off];
        __syncthreads();
    }
    int prefix = red[0];
    if (gid < N_ENT) {
        int val = prefix + sh[tid] - v;
        g_rowptr[gid] = val;
        g_cur[gid] = val;
    }
    if (b == 0 && tid == 0) g_rowptr[N_ENT] = NEDGE;
}

__global__ void k_scatter(const int* __restrict__ rows, const int* __restrict__ cols,
                          const float* __restrict__ vals) {
    int gid = blockIdx.x * blockDim.x + threadIdx.x;
    if (gid < NEDGE) {
        int r = rows[gid];
        int pos = atomicAdd(&g_cur[r], 1);
        g_pedge[pos] = make_int2(cols[gid], __float_as_int(vals[gid]));
    }
}

// ---------------- persistent HMMA layer GEMM 1 (+ wmat), reg-prefetched f32 input --------
// SMEM: WH 32K | WL 32K | X buf0 H/L 64K | X buf1 H/L 64K = 192 KB.
#define P1_WH  0
#define P1_WL  32768
#define P1_X0H 65536
#define P1_X0L 98304
#define P1_X1H 131072
#define P1_X1L 163840
#define P1_SMEM 196608
#define TOT1 (N_TILES + BATCH / 128)    // 399

__global__ void __launch_bounds__(512, 1) k_hgemm1p(
        const float* __restrict__ E, const float* __restrict__ R,
        const int* __restrict__ init_ind, const int* __restrict__ batch_rel,
        short* __restrict__ outA, float* __restrict__ outW) {
    extern __shared__ char sm[];
    uint32_t smb = smem_u32(sm);
    int tid = threadIdx.x;
    int cta = blockIdx.x;

    // 399 = 103*3 + 45*2
    int start, cnt;
    if (cta < 103) { start = cta * 3; cnt = 3; }
    else           { start = 309 + (cta - 103) * 2; cnt = 2; }
    int end = start + cnt;

    int wid = tid >> 5, lane = tid & 31;
    int wm = wid >> 2, wn = wid & 3;
    int lrow = lane & 15, lkh = lane >> 4;
    int q = lane >> 2, p4 = lane & 3;

    auto load_w = [&](int job) {
        const uint4* wh = (const uint4*)(job == 0 ? g_WT1H : g_WTWH);
        const uint4* wl = (const uint4*)(job == 0 ? g_WT1L : g_WTWL);
        #pragma unroll
        for (int l = tid; l < 2048; l += 512) {
            int r = l >> 4, c = l & 15;
            uint32_t off = r * 256 + ((c ^ (r & 7)) << 4);
            *(uint4*)(sm + P1_WH + off) = wh[l];
            *(uint4*)(sm + P1_WL + off) = wl[l];
        }
    };
    float4 rx[8];
    auto load_x = [&](int t) {
        int job = (t < N_TILES) ? 0 : 1;
        const float* X = job == 0 ? E : R;
        const int* idx = job == 0 ? init_ind : batch_rel;
        int nrows = job == 0 ? N_ENT : BATCH;
        int rbase = job == 0 ? t * 128 : (t - N_TILES) * 128;
        #pragma unroll
        for (int k = 0; k < 4; k++) {
            int l = tid + k * 512;
            int r = l >> 4, c = l & 15;
            int gr = rbase + r;
            float4 v0 = make_float4(0.f, 0.f, 0.f, 0.f), v1 = v0;
            if (gr < nrows) {
                const float4* xp = (const float4*)X + (size_t)idx[gr] * 32 + c * 2;
                v0 = xp[0]; v1 = xp[1];
            }
            rx[k * 2] = v0; rx[k * 2 + 1] = v1;
        }
    };

    int cur_job = (start < N_TILES) ? 0 : 1;
    load_w(cur_job);
    load_x(start);
    int p = 0;

    for (int t = start; t < end; t++) {
        int job = (t < N_TILES) ? 0 : 1;
        if (job != cur_job) {
            __syncthreads();
            load_w(job);
            cur_job = job;
        }
        uint32_t xh = smb + (p ? P1_X1H : P1_X0H);
        uint32_t xl = smb + (p ? P1_X1L : P1_X0L);
        #pragma unroll
        for (int k = 0; k < 4; k++) {
            int l = tid + k * 512;
            int r = l >> 4, c = l & 15;
            uint32_t off = r * 256 + ((c ^ (r & 7)) << 4);
            uint2 h0, l0, h1, l1;
            split4(rx[k * 2], h0, l0); split4(rx[k * 2 + 1], h1, l1);
            *(uint4*)((char*)sm + (xh - smb) + off) = make_uint4(h0.x, h0.y, h1.x, h1.y);
            *(uint4*)((char*)sm + (xl - smb) + off) = make_uint4(l0.x, l0.y, l1.x, l1.y);
        }
        __syncthreads();

        if (t + 1 < end) load_x(t + 1);

        float acc[2][4][4];
        #pragma unroll
        for (int i = 0; i < 2; i++)
            #pragma unroll
            for (int j = 0; j < 4; j++)
                #pragma unroll
                for (int f = 0; f < 4; f++) acc[i][j][f] = 0.f;

        mma_tile_3term16(xh, xl, smb + P1_WH, smb + P1_WL, wm, wn, lrow, lkh, acc);

        int nrows = (job == 0) ? N_ENT : BATCH;
        int rbase = (job == 0) ? t * 128 : (t - N_TILES) * 128;
        #pragma unroll
        for (int i = 0; i < 2; i++) {
            int r0 = rbase + wm * 32 + i * 16 + q;
            #pragma unroll
            for (int j = 0; j < 4; j++) {
                int n = wn * 32 + j * 8 + p4 * 2;
                if (job == 0) {
                    uint32_t* oq = (uint32_t*)outA;
                    if (r0 < nrows)
                        oq[r0 * 64 + (n >> 1)] = q2(acc[i][j][0], acc[i][j][1]);
                    if (r0 + 8 < nrows)
                        oq[(r0 + 8) * 64 + (n >> 1)] = q2(acc[i][j][2], acc[i][j][3]);
                } else {
                    if (r0 < nrows)
                        *(float2*)(outW + (size_t)r0 * DIM + n) = make_float2(acc[i][j][0], acc[i][j][1]);
                    if (r0 + 8 < nrows)
                        *(float2*)(outW + (size_t)(r0 + 8) * DIM + n) = make_float2(acc[i][j][2], acc[i][j][3]);
                }
            }
        }
        p ^= 1;
    }
}

// ---------------- persistent HMMA layer GEMM 2, cp.async bf16 input, int16 out ----------
#define P2_WH 0
#define P2_WL 32768
#define P2_X0 65536
#define P2_X1 131072
#define P2_SMEM 196608

__global__ void __launch_bounds__(512, 1) k_hgemm2p(short* __restrict__ out) {
    extern __shared__ char sm[];
    uint32_t smb = smem_u32(sm);
    int tid = threadIdx.x;
    int cta = blockIdx.x;

    // 391 = 95*3 + 53*2
    int start, cnt;
    if (cta < 95) { start = cta * 3; cnt = 3; }
    else          { start = 285 + (cta - 95) * 2; cnt = 2; }
    int end = start + cnt;

    int wid = tid >> 5, lane = tid & 31;
    int wm = wid >> 2, wn = wid & 3;
    int lrow = lane & 15, lkh = lane >> 4;
    int q = lane >> 2, p4 = lane & 3;

    const uint4* xh = (const uint4*)g_h1H;
    const uint4* xl = (const uint4*)g_h1L;

    auto prefetch_x = [&](int t, uint32_t dst) {
        size_t base = (size_t)t * 2048;
        #pragma unroll
        for (int l = tid; l < 2048; l += 512) {
            int r = l >> 4, c = l & 15;
            uint32_t off = r * 256 + ((c ^ (r & 7)) << 4);
            cp16(dst + off,         xh + base + l);
            cp16(dst + 32768 + off, xl + base + l);
        }
    };

    {
        const uint4* wh = (const uint4*)g_WT2H;
        const uint4* wl = (const uint4*)g_WT2L;
        #pragma unroll
        for (int l = tid; l < 2048; l += 512) {
            int r = l >> 4, c = l & 15;
            uint32_t off = r * 256 + ((c ^ (r & 7)) << 4);
            cp16(smb + P2_WH + off, wh + l);
            cp16(smb + P2_WL + off, wl + l);
        }
        prefetch_x(start, smb + P2_X0);
        asm volatile("cp.async.commit_group;" ::: "memory");
        asm volatile("cp.async.wait_group 0;" ::: "memory");
    }
    __syncthreads();

    int p = 0;
    for (int t = start; t < end; t++) {
        if (t + 1 < end) {
            prefetch_x(t + 1, smb + (p ? P2_X0 : P2_X1));
            asm volatile("cp.async.commit_group;" ::: "memory");
        }

        uint32_t xb = smb + (p ? P2_X1 : P2_X0);
        float acc[2][4][4];
        #pragma unroll
        for (int i = 0; i < 2; i++)
            #pragma unroll
            for (int j = 0; j < 4; j++)
                #pragma unroll
                for (int f = 0; f < 4; f++) acc[i][j][f] = 0.f;

        mma_tile_3term16(xb, xb + 32768, smb + P2_WH, smb + P2_WL, wm, wn, lrow, lkh, acc);

        int rbase = t * 128;
        uint32_t* oq = (uint32_t*)out;
        #pragma unroll
        for (int i = 0; i < 2; i++) {
            int r0 = rbase + wm * 32 + i * 16 + q;
            #pragma unroll
            for (int j = 0; j < 4; j++) {
                int n = wn * 32 + j * 8 + p4 * 2;
                if (r0 < N_ENT)
                    oq[r0 * 64 + (n >> 1)] = q2(acc[i][j][0], acc[i][j][1]);
                if (r0 + 8 < N_ENT)
                    oq[(r0 + 8) * 64 + (n >> 1)] = q2(acc[i][j][2], acc[i][j][3]);
            }
        }

        if (t + 1 < end) {
            asm volatile("cp.async.wait_group 0;" ::: "memory");
            __syncthreads();
        }
        p ^= 1;
    }
}

// ---------------- SpMM 1: h1 = split(relu(b1 + A @ q(src))), int16 gather, 4-way ---------
__global__ void k_spmm1(const short* __restrict__ src, const float* __restrict__ bias) {
    int w = (blockIdx.x * blockDim.x + threadIdx.x) >> 5;
    int lane = threadIdx.x & 31;
    if (w >= N_ENT) return;
    int s = g_rowptr[w], e = g_rowptr[w + 1];
    const short4* s4 = (const short4*)src;
    float4 a0 = ((const float4*)bias)[lane];
    float4 a1 = make_float4(0.f, 0.f, 0.f, 0.f), a2 = a1, a3 = a1;
    int j = s;
    for (; j + 4 <= e; j += 4) {
        int2 p0 = g_pedge[j], p1 = g_pedge[j + 1], p2 = g_pedge[j + 2], p3 = g_pedge[j + 3];
        short4 x0 = s4[(size_t)p0.x * 32 + lane];
        short4 x1 = s4[(size_t)p1.x * 32 + lane];
        short4 x2 = s4[(size_t)p2.x * 32 + lane];
        short4 x3 = s4[(size_t)p3.x * 32 + lane];
        float v0 = __int_as_float(p0.y) * INV_QS, v1 = __int_as_float(p1.y) * INV_QS;
        float v2 = __int_as_float(p2.y) * INV_QS, v3 = __int_as_float(p3.y) * INV_QS;
        a0.x += v0 * (float)x0.x; a0.y += v0 * (float)x0.y; a0.z += v0 * (float)x0.z; a0.w += v0 * (float)x0.w;
        a1.x += v1 * (float)x1.x; a1.y += v1 * (float)x1.y; a1.z += v1 * (float)x1.z; a1.w += v1 * (float)x1.w;
        a2.x += v2 * (float)x2.x; a2.y += v2 * (float)x2.y; a2.z += v2 * (float)x2.z; a2.w += v2 * (float)x2.w;
        a3.x += v3 * (float)x3.x; a3.y += v3 * (float)x3.y; a3.z += v3 * (float)x3.z; a3.w += v3 * (float)x3.w;
    }
    for (; j < e; j++) {
        int2 pe = g_pedge[j];
        float v = __int_as_float(pe.y) * INV_QS;
        short4 x = s4[(size_t)pe.x * 32 + lane];
        a0.x += v * (float)x.x; a0.y += v * (float)x.y; a0.z += v * (float)x.z; a0.w += v * (float)x.w;
    }
    a0.x += a1.x + a2.x + a3.x; a0.y += a1.y + a2.y + a3.y;
    a0.z += a1.z + a2.z + a3.z; a0.w += a1.w + a2.w + a3.w;
    a0.x = fmaxf(a0.x, 0.f); a0.y = fmaxf(a0.y, 0.f);
    a0.z = fmaxf(a0.z, 0.f); a0.w = fmaxf(a0.w, 0.f);
    uint2 hi, lo;
    split4(a0, hi, lo);
    ((uint2*)g_h1H)[w * 32 + lane] = hi;
    ((uint2*)g_h1L)[w * 32 + lane] = lo;
}

// ---------------- SpMM 2 fused: final = E[init] + relu(b2 + A @ q(src)); -> splits only --
__global__ void k_spmm2f(const short* __restrict__ src, const float* __restrict__ bias,
                         const float* __restrict__ E, const int* __restrict__ idx) {
    int w = (blockIdx.x * blockDim.x + threadIdx.x) >> 5;
    int lane = threadIdx.x & 31;
    if (w >= N_ENT) return;
    int s = g_rowptr[w], e = g_rowptr[w + 1];
    const short4* s4 = (const short4*)src;
    float4 a0 = ((const float4*)bias)[lane];
    float4 a1 = make_float4(0.f, 0.f, 0.f, 0.f), a2 = a1, a3 = a1;
    int j = s;
    for (; j + 4 <= e; j += 4) {
        int2 p0 = g_pedge[j], p1 = g_pedge[j + 1], p2 = g_pedge[j + 2], p3 = g_pedge[j + 3];
        short4 x0 = s4[(size_t)p0.x * 32 + lane];
        short4 x1 = s4[(size_t)p1.x * 32 + lane];
        short4 x2 = s4[(size_t)p2.x * 32 + lane];
        short4 x3 = s4[(size_t)p3.x * 32 + lane];
        float v0 = __int_as_float(p0.y) * INV_QS, v1 = __int_as_float(p1.y) * INV_QS;
        float v2 = __int_as_float(p2.y) * INV_QS, v3 = __int_as_float(p3.y) * INV_QS;
        a0.x += v0 * (float)x0.x; a0.y += v0 * (float)x0.y; a0.z += v0 * (float)x0.z; a0.w += v0 * (float)x0.w;
        a1.x += v1 * (float)x1.x; a1.y += v1 * (float)x1.y; a1.z += v1 * (float)x1.z; a1.w += v1 * (float)x1.w;
        a2.x += v2 * (float)x2.x; a2.y += v2 * (float)x2.y; a2.z += v2 * (float)x2.z; a2.w += v2 * (float)x2.w;
        a3.x += v3 * (float)x3.x; a3.y += v3 * (float)x3.y; a3.z += v3 * (float)x3.z; a3.w += v3 * (float)x3.w;
    }
    for (; j < e; j++) {
        int2 pe = g_pedge[j];
        float v = __int_as_float(pe.y) * INV_QS;
        short4 x = s4[(size_t)pe.x * 32 + lane];
        a0.x += v * (float)x.x; a0.y += v * (float)x.y; a0.z += v * (float)x.z; a0.w += v * (float)x.w;
    }
    a0.x += a1.x + a2.x + a3.x; a0.y += a1.y + a2.y + a3.y;
    a0.z += a1.z + a2.z + a3.z; a0.w += a1.w + a2.w + a3.w;
    float4 e4 = ((const float4*)E)[(size_t)idx[w] * 32 + lane];
    e4.x += fmaxf(a0.x, 0.f); e4.y += fmaxf(a0.y, 0.f);
    e4.z += fmaxf(a0.z, 0.f); e4.w += fmaxf(a0.w, 0.f);
    uint2 hi, lo;
    split4(e4, hi, lo);
    ((uint2*)g_finalH)[w * 32 + lane] = hi;
    ((uint2*)g_finalL)[w * 32 + lane] = lo;
}

// ---------------- vm = bn1(bn0(unsplit(final)[bh]) * wmat); + split ----------------
__global__ void k_vm_split(const int* __restrict__ bh,
                           const float* __restrict__ g0, const float* __restrict__ b0,
                           const float* __restrict__ g1, const float* __restrict__ b1) {
    int gid = blockIdx.x * blockDim.x + threadIdx.x;
    if (gid >= BATCH * 32) return;
    int b = gid >> 5, qq = gid & 31;
    float s = rsqrtf(1.0f + BN_EPS);
    float4 G0 = ((const float4*)g0)[qq], B0 = ((const float4*)b0)[qq];
    float4 G1 = ((const float4*)g1)[qq], B1 = ((const float4*)b1)[qq];
    size_t fi = (size_t)bh[b] * 32 + qq;
    float4 x = unsplit4(((const uint2*)g_finalH)[fi], ((const uint2*)g_finalL)[fi]);
    float4 wm = ((const float4*)g_wmat)[gid];
    float4 r;
    r.x = ((x.x * (G0.x * s) + B0.x) * wm.x) * (G1.x * s) + B1.x;
    r.y = ((x.y * (G0.y * s) + B0.y) * wm.y) * (G1.y * s) + B1.y;
    r.z = ((x.z * (G0.z * s) + B0.z) * wm.z) * (G1.z * s) + B1.z;
    r.w = ((x.w * (G0.w * s) + B0.w) * wm.w) * (G1.w * s) + B1.w;
    uint2 hi, lo;
    split4(r, hi, lo);
    ((uint2*)g_vmH)[gid] = hi;
    ((uint2*)g_vmL)[gid] = lo;
}

// ---------------- persistent double-buffered big GEMM, 512 thr --------------------------
#define PG_AH 0
#define PG_AL 32768
#define PG_B0 65536
#define PG_B1 131072
#define PG_SMEM 196608

__global__ void __launch_bounds__(512, 1) k_biggemm_persist(float* __restrict__ out) {
    extern __shared__ char sm[];
    uint32_t smb = smem_u32(sm);
    int tid = threadIdx.x;
    int cta = blockIdx.x;

    // balanced contiguous chunks: 3128 = 20*22 + 128*21
    int start, cnt;
    if (cta < 20) { start = cta * 22; cnt = 22; }
    else          { start = 440 + (cta - 20) * 21; cnt = 21; }
    int end = start + cnt;

    const uint4* Ah = (const uint4*)g_vmH;
    const uint4* Al = (const uint4*)g_vmL;
    const uint4* Bh = (const uint4*)g_finalH;
    const uint4* Bl = (const uint4*)g_finalL;

    int wid = tid >> 5, lane = tid & 31;
    int wm = wid >> 2, wn = wid & 3;
    int lrow = lane & 15, lkh = lane >> 4;
    int q = lane >> 2, p4 = lane & 3;

    int cur_b = -1, buf = 0, loaded = 0;

    for (int t = start; t < end; t++) {
        int b = t / N_TILES, n = t - b * N_TILES;
        __syncthreads();

        if (!loaded) {
            if (b != cur_b) {
                int bbase = b * 128;
                #pragma unroll
                for (int l = tid; l < 2048; l += 512) {
                    int r = l >> 4, c = l & 15;
                    uint32_t off = r * 256 + ((c ^ (r & 7)) << 4);
                    cp16(smb + PG_AH + off, Ah + (size_t)(bbase + r) * 16 + c);
                    cp16(smb + PG_AL + off, Al + (size_t)(bbase + r) * 16 + c);
                }
                cur_b = b;
            }
            int nbase = n * 128;
            uint32_t sb = smb + (buf ? PG_B1 : PG_B0);
            #pragma unroll
            for (int l = tid; l < 2048; l += 512) {
                int r = l >> 4, c = l & 15;
                uint32_t off = r * 256 + ((c ^ (r & 7)) << 4);
                cp16(sb + off,         Bh + (size_t)(nbase + r) * 16 + c);
                cp16(sb + 32768 + off, Bl + (size_t)(nbase + r) * 16 + c);
            }
            asm volatile("cp.async.commit_group;" ::: "memory");
        }

        int pf = 0;
        if (t + 1 < end) {
            int b2 = (t + 1) / N_TILES, n2 = (t + 1) - b2 * N_TILES;
            if (b2 == cur_b) {
                int nbase2 = n2 * 128;
                uint32_t sb2 = smb + (buf ? PG_B0 : PG_B1);
                #pragma unroll
                for (int l = tid; l < 2048; l += 512) {
                    int r = l >> 4, c = l & 15;
                    uint32_t off = r * 256 + ((c ^ (r & 7)) << 4);
                    cp16(sb2 + off,         Bh + (size_t)(nbase2 + r) * 16 + c);
                    cp16(sb2 + 32768 + off, Bl + (size_t)(nbase2 + r) * 16 + c);
                }
                asm volatile("cp.async.commit_group;" ::: "memory");
                pf = 1;
            }
        }
        if (pf) asm volatile("cp.async.wait_group 1;" ::: "memory");
        else    asm volatile("cp.async.wait_group 0;" ::: "memory");
        __syncthreads();

        uint32_t sb = smb + (buf ? PG_B1 : PG_B0);
        float acc[2][4][4];
        #pragma unroll
        for (int i = 0; i < 2; i++)
            #pragma unroll
            for (int j = 0; j < 4; j++)
                #pragma unroll
                for (int f = 0; f < 4; f++) acc[i][j][f] = 0.f;

        mma_tile_3term16(smb + PG_AH, smb + PG_AL, sb, sb + 32768,
                         wm, wn, lrow, lkh, acc);

        int bbase = b * 128, nbase = n * 128;
        #pragma unroll
        for (int i = 0; i < 2; i++) {
            int brow = bbase + wm * 32 + i * 16 + q;
            #pragma unroll
            for (int j = 0; j < 4; j++) {
                int nn = nbase + wn * 32 + j * 8 + p4 * 2;
                if (nn < N_ENT) {
                    float2 o0, o1;
                    o0.x = sigmoidf(acc[i][j][0]); o0.y = sigmoidf(acc[i][j][1]);
                    o1.x = sigmoidf(acc[i][j][2]); o1.y = sigmoidf(acc[i][j][3]);
                    *(float2*)(out + (size_t)brow * N_ENT + nn) = o0;
                    *(float2*)(out + (size_t)(brow + 8) * N_ENT + nn) = o1;
                }
            }
        }

        loaded = pf;
        buf ^= 1;
    }
}

// ---------------- orchestration ----------------
extern "C" void kernel_launch(void* const* d_in, const int* in_sizes, int n_in,
                              void* d_out, int out_size) {
    const float* E_emb     = (const float*)d_in[0];
    const float* R_emb     = (const float*)d_in[1];
    const float* W1        = (const float*)d_in[2];
    const float* b1        = (const float*)d_in[3];
    const float* W2        = (const float*)d_in[4];
    const float* b2        = (const float*)d_in[5];
    const float* W         = (const float*)d_in[6];
    const float* adj_vals  = (const float*)d_in[7];
    const float* bn0_gamma = (const float*)d_in[8];
    const float* bn0_beta  = (const float*)d_in[9];
    const float* bn1_gamma = (const float*)d_in[10];
    const float* bn1_beta  = (const float*)d_in[11];
    const int*   batch_head = (const int*)d_in[12];
    const int*   batch_rel  = (const int*)d_in[13];
    const int*   init_ind   = (const int*)d_in[14];
    const int*   adj_rows   = (const int*)d_in[15];
    const int*   adj_cols   = (const int*)d_in[16];
    float* out = (float*)d_out;

    short* pA;
    float* pWM;
    cudaGetSymbolAddress((void**)&pA, g_bufA);
    cudaGetSymbolAddress((void**)&pWM, g_wmat);

    cudaFuncSetAttribute(k_hgemm1p, cudaFuncAttributeMaxDynamicSharedMemorySize, P1_SMEM);
    cudaFuncSetAttribute(k_hgemm2p, cudaFuncAttributeMaxDynamicSharedMemorySize, P2_SMEM);
    cudaFuncSetAttribute(k_biggemm_persist, cudaFuncAttributeMaxDynamicSharedMemorySize, PG_SMEM);

    const int EDGE_BLKS = (NEDGE + 255) / 256;          // 3125
    const int ENT_BLKS  = (N_ENT + 255) / 256;          // 196
    const int ROWW_BLKS = (N_ENT * 32 + 255) / 256;     // 6250

    // 1. histogram + weight splits (+ g_bsum reset)
    k_prep<<<EDGE_BLKS + 192, 256>>>(adj_rows, EDGE_BLKS, W1, W2, W);
    // 2. single-launch scan (also zeroes g_cnt for next launch)
    k_scan_lb<<<ENT_BLKS, 256>>>();
    // 3. CSR scatter
    k_scatter<<<EDGE_BLKS, 256>>>(adj_rows, adj_cols, adj_vals);
    // 4. persistent layer-1 GEMM (int16 out) + wmat GEMM (f32 out)
    k_hgemm1p<<<NCTA, 512, P1_SMEM>>>(E_emb, R_emb, init_ind, batch_rel, pA, pWM);
    // 5. SpMM1 int16-gather (+relu+split)
    k_spmm1<<<ROWW_BLKS, 256>>>(pA, b1);
    // 6. persistent layer-2 GEMM (bf16 in, int16 out)
    k_hgemm2p<<<NCTA, 512, P2_SMEM>>>(pA);
    // 7. SpMM2 int16-gather (+residual+relu+split, splits only)
    k_spmm2f<<<ROWW_BLKS, 256>>>(pA, b2, E_emb, init_ind);
    // 8. vm (+split, reconstructs final from splits)
    k_vm_split<<<(BATCH * 32 + 255) / 256, 256>>>(batch_head, bn0_gamma, bn0_beta, bn1_gamma, bn1_beta);
    // 9. persistent tensor-core scoring GEMM + sigmoid
    k_biggemm_persist<<<NCTA, 512, PG_SMEM>>>(out);
}